// round 1
// baseline (speedup 1.0000x reference)
#include <cuda_runtime.h>

#define NB   1024   // assets
#define NT   4096   // timesteps
#define NH   20     // hidden
#define NG   80     // 4*NH gates

// scratch: last hidden state per asset (no cudaMalloc allowed)
__device__ float g_hlast[NB * NH];

using u64 = unsigned long long;

__device__ __forceinline__ u64 pack2(float lo, float hi) {
    u64 r;
    asm("mov.b64 %0, {%1, %2};" : "=l"(r)
        : "r"(__float_as_uint(lo)), "r"(__float_as_uint(hi)));
    return r;
}
__device__ __forceinline__ float2 unpack2(u64 v) {
    unsigned lo, hi;
    asm("mov.b64 {%0, %1}, %2;" : "=r"(lo), "=r"(hi) : "l"(v));
    return make_float2(__uint_as_float(lo), __uint_as_float(hi));
}
// packed 2x fp32 FMA (fma pipe, 2 lane-FMAs per instruction)
__device__ __forceinline__ u64 ffma2(u64 a, u64 b, u64 c) {
    u64 d;
    asm("fma.rn.f32x2 %0, %1, %2, %3;" : "=l"(d) : "l"(a), "l"(b), "l"(c));
    return d;
}
__device__ __forceinline__ float ex2a(float x) {
    float y; asm("ex2.approx.f32 %0, %1;" : "=f"(y) : "f"(x)); return y;
}
__device__ __forceinline__ float rcpa(float x) {
    float y; asm("rcp.approx.f32 %0, %1;" : "=f"(y) : "f"(x)); return y;
}

// unified activation: sigmoid(x) = rcp(1 + 2^(-log2e*x))
//                     tanh(x)    = 2*rcp(1 + 2^(-2*log2e*x)) - 1
__device__ __forceinline__ float act_eval(float v, float pm, float aa, float ab) {
    float e = ex2a(pm * v);
    float r = rcpa(1.0f + e);
    return fmaf(aa, r, ab);
}

// one warp == one asset. Lane l owns gates l, l+32, and (l<16) l+64.
__global__ void __launch_bounds__(32)
lstm_kernel(const float* __restrict__ x,
            const float* __restrict__ Wih,
            const float* __restrict__ Whh,
            const float* __restrict__ bih,
            const float* __restrict__ bhh)
{
    const int a = blockIdx.x;
    const int l = threadIdx.x;
    const bool hasC = (l < 16);

    // s_act: activated gates at unit*4+type, +4 dump slots for lanes 16..31's C-slot
    __shared__ __align__(16) float s_act[NG + 4];
    // s_h: h[0..19], +4 dump slots for lanes 20..31
    __shared__ __align__(16) float s_h[NH + 4];

    const int gA = l;
    const int gB = l + 32;
    const int gC = hasC ? (l + 64) : 0;   // safe index when unused

    // ---- per-lane constants (loaded once, broadcast via L2) ----
    u64 wA[10], wB[10], wC[10];
    {
        const u64* pa = reinterpret_cast<const u64*>(Whh + gA * NH);
        const u64* pb = reinterpret_cast<const u64*>(Whh + gB * NH);
        const u64* pc = reinterpret_cast<const u64*>(Whh + gC * NH);
#pragma unroll
        for (int k = 0; k < 10; k++) {
            wA[k] = pa[k];
            wB[k] = pb[k];
            wC[k] = hasC ? pc[k] : 0ull;   // 0.0f pair -> garbage lanes compute 0
        }
    }
    const float wiA0 = Wih[gA * 3 + 0], wiA1 = Wih[gA * 3 + 1], wiA2 = Wih[gA * 3 + 2];
    const float wiB0 = Wih[gB * 3 + 0], wiB1 = Wih[gB * 3 + 1], wiB2 = Wih[gB * 3 + 2];
    const float wiC0 = hasC ? Wih[gC * 3 + 0] : 0.f;
    const float wiC1 = hasC ? Wih[gC * 3 + 1] : 0.f;
    const float wiC2 = hasC ? Wih[gC * 3 + 2] : 0.f;
    const float bA = bih[gA] + bhh[gA];
    const float bB = bih[gB] + bhh[gB];
    const float bC = hasC ? (bih[gC] + bhh[gC]) : 0.f;

    const float LOG2E  = 1.44269504088896340f;
    const float LOG2E2 = 2.88539008177792681f;
    // torch gate order i,f,g,o -> type g/20; tanh only for type 2 (g in [40,60))
    const bool tA = (gA >= 40 && gA < 60);
    const bool tB = (gB >= 40 && gB < 60);
    const bool tC = (gC >= 40 && gC < 60);
    const float pmA = tA ? -LOG2E2 : -LOG2E, aaA = tA ? 2.f : 1.f, abA = tA ? -1.f : 0.f;
    const float pmB = tB ? -LOG2E2 : -LOG2E, aaB = tB ? 2.f : 1.f, abB = tB ? -1.f : 0.f;
    const float pmC = tC ? -LOG2E2 : -LOG2E, aaC = tC ? 2.f : 1.f, abC = tC ? -1.f : 0.f;

    // scatter addresses: act[(g%20)*4 + g/20]; non-owning lanes dump to slot 80
    const int adA = (gA % NH) * 4 + gA / NH;
    const int adB = (gB % NH) * 4 + gB / NH;
    const int adC = hasC ? ((gC % NH) * 4 + gC / NH) : NG;
    const int adH = (l < NH) ? l : NH;          // h dump slot 20
    const int adR = (l < NH) ? l : 0;           // safe float4 read index

    // ---- x pointers: x[f][a][t], contiguous in t ----
    const float* x0p = x + (size_t)a * NT;
    const float* x1p = x0p + (size_t)NB * NT;
    const float* x2p = x1p + (size_t)NB * NT;

    float cx0 = x0p[0], cx1 = x1p[0], cx2 = x2p[0];

    u64 hk[10];
#pragma unroll
    for (int k = 0; k < 10; k++) hk[k] = 0ull;   // h0 = 0
    float c = 0.f, hval = 0.f;

    const u64* sh64 = reinterpret_cast<const u64*>(s_h);

    for (int t = 0; t < NT; t++) {
        const int tn = (t < NT - 1) ? (t + 1) : t;
        const float nx0 = x0p[tn];
        const float nx1 = x1p[tn];
        const float nx2 = x2p[tn];

        // gate pre-activations: bias + x-part, then packed K-dot over h
        float iA = fmaf(cx2, wiA2, fmaf(cx1, wiA1, fmaf(cx0, wiA0, bA)));
        float iB = fmaf(cx2, wiB2, fmaf(cx1, wiB1, fmaf(cx0, wiB0, bB)));
        float iC = fmaf(cx2, wiC2, fmaf(cx1, wiC1, fmaf(cx0, wiC0, bC)));
        u64 accA = pack2(iA, 0.f);
        u64 accB = pack2(iB, 0.f);
        u64 accC = pack2(iC, 0.f);
#pragma unroll
        for (int k = 0; k < 10; k++) {
            accA = ffma2(hk[k], wA[k], accA);
            accB = ffma2(hk[k], wB[k], accB);
            accC = ffma2(hk[k], wC[k], accC);
        }
        float2 pA = unpack2(accA);
        float2 pB = unpack2(accB);
        float2 pC = unpack2(accC);
        const float vA = pA.x + pA.y;
        const float vB = pB.x + pB.y;
        const float vC = pC.x + pC.y;

        s_act[adA] = act_eval(vA, pmA, aaA, abA);
        s_act[adB] = act_eval(vB, pmB, aaB, abB);
        s_act[adC] = act_eval(vC, pmC, aaC, abC);
        __syncwarp();

        // per-unit state update (lanes >=20 compute harmless replicas into dump slots)
        {
            float4 v = *reinterpret_cast<const float4*>(&s_act[adR * 4]);
            // v.x=i, v.y=f, v.z=g~, v.w=o
            float cn = fmaf(v.y, c, v.x * v.z);
            c = cn;
            float e2 = ex2a(-LOG2E2 * cn);
            float th = fmaf(2.f, rcpa(1.0f + e2), -1.f);
            hval = v.w * th;
            s_h[adH] = hval;
        }
        __syncwarp();

#pragma unroll
        for (int k = 0; k < 10; k++) hk[k] = sh64[k];

        cx0 = nx0; cx1 = nx1; cx2 = nx2;
    }

    if (l < NH) g_hlast[a * NH + l] = hval;
}

// head: y = relu(h) @ fc_w^T + fc_b ; z = conv over [lastAction, y];
// fc+conv compose linearly: z_b = cw0*la_b + relu(h_b)·u + s,
//   u_k = sum_j cw[1+j]*fc_w[j,k],  s = sum_j cw[1+j]*fc_b[j] + conv_b
__global__ void __launch_bounds__(NB)
head_kernel(const float* __restrict__ la,
            const float* __restrict__ fcw,
            const float* __restrict__ fcb,
            const float* __restrict__ cw,
            const float* __restrict__ cb,
            float* __restrict__ out)
{
    const int b = threadIdx.x;
    __shared__ float s_u[NH];
    __shared__ float s_s;
    __shared__ float s_red[32];
    __shared__ float s_bcast;

    if (b < NH) {
        float u = 0.f;
#pragma unroll
        for (int j = 0; j < NH; j++) u = fmaf(cw[1 + j], fcw[j * NH + b], u);
        s_u[b] = u;
    }
    if (b == NH) {
        float s = cb[0];
#pragma unroll
        for (int j = 0; j < NH; j++) s = fmaf(cw[1 + j], fcb[j], s);
        s_s = s;
    }
    __syncthreads();

    float z = fmaf(cw[0], la[b], s_s);
    const float* h = &g_hlast[b * NH];
#pragma unroll
    for (int j = 0; j < NH; j++) z = fmaf(fmaxf(h[j], 0.f), s_u[j], z);

    // block max over {z_b} (cash logit 1.0 folded in at the end)
    float m = z;
#pragma unroll
    for (int off = 16; off > 0; off >>= 1)
        m = fmaxf(m, __shfl_xor_sync(0xffffffffu, m, off));
    if ((b & 31) == 0) s_red[b >> 5] = m;
    __syncthreads();
    if (b < 32) {
        float v = s_red[b];
#pragma unroll
        for (int off = 16; off > 0; off >>= 1)
            v = fmaxf(v, __shfl_xor_sync(0xffffffffu, v, off));
        if (b == 0) s_bcast = fmaxf(v, 1.0f);
    }
    __syncthreads();
    m = s_bcast;

    float e = __expf(z - m);
    float s = e;
#pragma unroll
    for (int off = 16; off > 0; off >>= 1)
        s += __shfl_xor_sync(0xffffffffu, s, off);
    if ((b & 31) == 0) s_red[b >> 5] = s;
    __syncthreads();
    if (b < 32) {
        float v = s_red[b];
#pragma unroll
        for (int off = 16; off > 0; off >>= 1)
            v += __shfl_xor_sync(0xffffffffu, v, off);
        if (b == 0) s_bcast = v + __expf(1.0f - m);
    }
    __syncthreads();
    const float denom = s_bcast;

    out[1 + b] = e / denom;
    if (b == 0) out[0] = __expf(1.0f - m) / denom;
}

extern "C" void kernel_launch(void* const* d_in, const int* in_sizes, int n_in,
                              void* d_out, int out_size)
{
    const float* x   = (const float*)d_in[0];
    const float* la  = (const float*)d_in[1];
    const float* Wih = (const float*)d_in[2];
    const float* Whh = (const float*)d_in[3];
    const float* bih = (const float*)d_in[4];
    const float* bhh = (const float*)d_in[5];
    const float* fcw = (const float*)d_in[6];
    const float* fcb = (const float*)d_in[7];
    const float* cw  = (const float*)d_in[8];
    const float* cb  = (const float*)d_in[9];

    lstm_kernel<<<NB, 32>>>(x, Wih, Whh, bih, bhh);
    head_kernel<<<1, NB>>>(la, fcw, fcb, cw, cb, (float*)d_out);
}

// round 2
// speedup vs baseline: 1.0319x; 1.0319x over previous
#include <cuda_runtime.h>

#define NB   1024   // assets
#define NT   4096   // timesteps
#define NH   20     // hidden

// scratch: last hidden state per asset (no cudaMalloc allowed)
__device__ float g_hlast[NB * NH];

using u64 = unsigned long long;

__device__ __forceinline__ u64 pack2(float lo, float hi) {
    u64 r;
    asm("mov.b64 %0, {%1, %2};" : "=l"(r)
        : "r"(__float_as_uint(lo)), "r"(__float_as_uint(hi)));
    return r;
}
__device__ __forceinline__ float2 unpack2(u64 v) {
    unsigned lo, hi;
    asm("mov.b64 {%0, %1}, %2;" : "=r"(lo), "=r"(hi) : "l"(v));
    return make_float2(__uint_as_float(lo), __uint_as_float(hi));
}
__device__ __forceinline__ u64 ffma2(u64 a, u64 b, u64 c) {
    u64 d;
    asm("fma.rn.f32x2 %0, %1, %2, %3;" : "=l"(d) : "l"(a), "l"(b), "l"(c));
    return d;
}
__device__ __forceinline__ u64 add2(u64 a, u64 b) {
    u64 d;
    asm("add.rn.f32x2 %0, %1, %2;" : "=l"(d) : "l"(a), "l"(b));
    return d;
}
__device__ __forceinline__ float ex2a(float x) {
    float y; asm("ex2.approx.f32 %0, %1;" : "=f"(y) : "f"(x)); return y;
}
__device__ __forceinline__ float rcpa(float x) {
    float y; asm("rcp.approx.f32 %0, %1;" : "=f"(y) : "f"(x)); return y;
}

#define LOG2E  1.44269504088896340f
#define LOG2E2 2.88539008177792681f

// one warp == one asset. Lane l owns gates l (A), l+32 (B), and (l<16) l+64 (C).
// Gate order (torch): i[0,20) f[20,40) g[40,60) o[60,80).
//   A-gates (0..31):  all sigmoid.  B-gates (32..63): mixed (tanh iff l in [8,28)).
//   C-gates (64..79): all sigmoid.
__global__ void __launch_bounds__(32)
lstm_kernel(const float* __restrict__ x,
            const float* __restrict__ Wih,
            const float* __restrict__ Whh,
            const float* __restrict__ bih,
            const float* __restrict__ bhh)
{
    const int a = blockIdx.x;
    const int l = threadIdx.x;
    const bool hasC = (l < 16);

    // double-buffered h exchange: one __syncwarp per step, conflict-free
    __shared__ __align__(16) float s_h[2][24];

    const int gA = l;
    const int gB = l + 32;
    const int gC = hasC ? (l + 64) : 0;

    // ---- per-lane constants ----
    u64 wA[10], wB[10], wC[10];
    {
        const u64* pa = reinterpret_cast<const u64*>(Whh + gA * NH);
        const u64* pb = reinterpret_cast<const u64*>(Whh + gB * NH);
        const u64* pc = reinterpret_cast<const u64*>(Whh + gC * NH);
#pragma unroll
        for (int k = 0; k < 10; k++) {
            wA[k] = pa[k];
            wB[k] = pb[k];
            wC[k] = hasC ? pc[k] : 0ull;
        }
    }
    const float wiA0 = Wih[gA * 3 + 0], wiA1 = Wih[gA * 3 + 1], wiA2 = Wih[gA * 3 + 2];
    const float wiB0 = Wih[gB * 3 + 0], wiB1 = Wih[gB * 3 + 1], wiB2 = Wih[gB * 3 + 2];
    const float wiC0 = hasC ? Wih[gC * 3 + 0] : 0.f;
    const float wiC1 = hasC ? Wih[gC * 3 + 1] : 0.f;
    const float wiC2 = hasC ? Wih[gC * 3 + 2] : 0.f;
    const float bA = bih[gA] + bhh[gA];
    const float bB = bih[gB] + bhh[gB];
    const float bC = hasC ? (bih[gC] + bhh[gC]) : 0.f;

    // B-gate activation params (A, C are pure sigmoid)
    const bool  tB  = (gB >= 40 && gB < 60);
    const float pmB = tB ? -LOG2E2 : -LOG2E;
    const float aaB = tB ? 2.f : 1.f;
    const float abB = tB ? -1.f : 0.f;

    // shuffle indices for the act gather (mod-32 congruence serves both reg sources)
    const int cF = (20 + l) & 31;   // f_u: lane(20+u).A  or lane(u-12).B
    const int cG = (8  + l) & 31;   // g_u: lane(u+8).B
    const int cO = (28 + l) & 31;   // o_u: lane(28+u).B  or lane(u-4).C

    // ---- x pointers: x[f][a][t], contiguous in t ----
    const float* p0 = x + (size_t)a * NT;
    const float* p1 = p0 + (size_t)NB * NT;
    const float* p2 = p1 + (size_t)NB * NT;

    float cx0 = p0[0], cx1 = p1[0], cx2 = p2[0];

    u64 hk[10];
#pragma unroll
    for (int k = 0; k < 10; k++) hk[k] = 0ull;
    float c = 0.f, hval = 0.f;

    auto step = [&](float X0, float X1, float X2, int buf) {
        // acc init carries bias + full x-part (off the critical h path)
        u64 a1 = pack2(fmaf(X0, wiA0, bA), X1 * wiA1);
        u64 a2 = pack2(X2 * wiA2, 0.f);
        u64 b1 = pack2(fmaf(X0, wiB0, bB), X1 * wiB1);
        u64 b2 = pack2(X2 * wiB2, 0.f);
        u64 c1 = pack2(fmaf(X0, wiC0, bC), X1 * wiC1);
        u64 c2 = pack2(X2 * wiC2, 0.f);
#pragma unroll
        for (int k = 0; k < 5; k++) {
            a1 = ffma2(hk[2*k],   wA[2*k],   a1);
            a2 = ffma2(hk[2*k+1], wA[2*k+1], a2);
            b1 = ffma2(hk[2*k],   wB[2*k],   b1);
            b2 = ffma2(hk[2*k+1], wB[2*k+1], b2);
            c1 = ffma2(hk[2*k],   wC[2*k],   c1);
            c2 = ffma2(hk[2*k+1], wC[2*k+1], c2);
        }
        float2 pA = unpack2(add2(a1, a2));
        float2 pB = unpack2(add2(b1, b2));
        float2 pC = unpack2(add2(c1, c2));
        const float vA = pA.x + pA.y;
        const float vB = pB.x + pB.y;
        const float vC = pC.x + pC.y;

        // activations (precise: ex2.approx + rcp.approx)
        const float actA = rcpa(1.0f + ex2a(-LOG2E * vA));           // sigmoid
        const float rB   = rcpa(1.0f + ex2a(pmB * vB));
        const float actB = fmaf(aaB, rB, abB);                        // sigmoid or tanh
        const float actC = rcpa(1.0f + ex2a(-LOG2E * vC));           // sigmoid

        // gather per-unit gates via shuffles (implicit warp sync; no smem, no conflicts)
        const float fA = __shfl_sync(0xffffffffu, actA, cF);
        const float fB = __shfl_sync(0xffffffffu, actB, cF);
        const float gg = __shfl_sync(0xffffffffu, actB, cG);
        const float oB = __shfl_sync(0xffffffffu, actB, cO);
        const float oC = __shfl_sync(0xffffffffu, actC, cO);
        const float f  = (l < 12) ? fA : fB;
        const float o  = (l < 4)  ? oB : oC;
        const float i  = actA;   // gate u is lane-local

        // state update (lanes >= 20 compute harmless junk, never stored)
        const float cn = fmaf(f, c, i * gg);
        c = cn;
        const float th = fmaf(2.f, rcpa(1.0f + ex2a(-LOG2E2 * cn)), -1.f);
        hval = o * th;

        if (l < NH) s_h[buf][l] = hval;
        __syncwarp();
        const ulonglong2* hp = reinterpret_cast<const ulonglong2*>(s_h[buf]);
        ulonglong2 q;
        q = hp[0]; hk[0] = q.x; hk[1] = q.y;
        q = hp[1]; hk[2] = q.x; hk[3] = q.y;
        q = hp[2]; hk[4] = q.x; hk[5] = q.y;
        q = hp[3]; hk[6] = q.x; hk[7] = q.y;
        q = hp[4]; hk[8] = q.x; hk[9] = q.y;
        // no second sync: next step writes the OTHER buffer (WAR moved across buffers)
    };

#pragma unroll 2
    for (int t = 0; t < NT - 1; t++) {
        const float nx0 = p0[1];
        const float nx1 = p1[1];
        const float nx2 = p2[1];
        p0++; p1++; p2++;
        step(cx0, cx1, cx2, t & 1);
        cx0 = nx0; cx1 = nx1; cx2 = nx2;
    }
    step(cx0, cx1, cx2, (NT - 1) & 1);   // peeled last step: no prefetch, no OOB

    if (l < NH) g_hlast[a * NH + l] = hval;
}

// head: fc + 1x1 conv compose linearly: z_b = cw0*la_b + relu(h_b)·u + s
__global__ void __launch_bounds__(NB)
head_kernel(const float* __restrict__ la,
            const float* __restrict__ fcw,
            const float* __restrict__ fcb,
            const float* __restrict__ cw,
            const float* __restrict__ cb,
            float* __restrict__ out)
{
    const int b = threadIdx.x;
    __shared__ float s_u[NH];
    __shared__ float s_s;
    __shared__ float s_red[32];
    __shared__ float s_bcast;

    if (b < NH) {
        float u = 0.f;
#pragma unroll
        for (int j = 0; j < NH; j++) u = fmaf(cw[1 + j], fcw[j * NH + b], u);
        s_u[b] = u;
    }
    if (b == NH) {
        float s = cb[0];
#pragma unroll
        for (int j = 0; j < NH; j++) s = fmaf(cw[1 + j], fcb[j], s);
        s_s = s;
    }
    __syncthreads();

    float z = fmaf(cw[0], la[b], s_s);
    const float* h = &g_hlast[b * NH];
#pragma unroll
    for (int j = 0; j < NH; j++) z = fmaf(fmaxf(h[j], 0.f), s_u[j], z);

    float m = z;
#pragma unroll
    for (int off = 16; off > 0; off >>= 1)
        m = fmaxf(m, __shfl_xor_sync(0xffffffffu, m, off));
    if ((b & 31) == 0) s_red[b >> 5] = m;
    __syncthreads();
    if (b < 32) {
        float v = s_red[b];
#pragma unroll
        for (int off = 16; off > 0; off >>= 1)
            v = fmaxf(v, __shfl_xor_sync(0xffffffffu, v, off));
        if (b == 0) s_bcast = fmaxf(v, 1.0f);
    }
    __syncthreads();
    m = s_bcast;

    float e = __expf(z - m);
    float s = e;
#pragma unroll
    for (int off = 16; off > 0; off >>= 1)
        s += __shfl_xor_sync(0xffffffffu, s, off);
    if ((b & 31) == 0) s_red[b >> 5] = s;
    __syncthreads();
    if (b < 32) {
        float v = s_red[b];
#pragma unroll
        for (int off = 16; off > 0; off >>= 1)
            v += __shfl_xor_sync(0xffffffffu, v, off);
        if (b == 0) s_bcast = v + __expf(1.0f - m);
    }
    __syncthreads();
    const float denom = s_bcast;

    out[1 + b] = e / denom;
    if (b == 0) out[0] = __expf(1.0f - m) / denom;
}

extern "C" void kernel_launch(void* const* d_in, const int* in_sizes, int n_in,
                              void* d_out, int out_size)
{
    const float* x   = (const float*)d_in[0];
    const float* la  = (const float*)d_in[1];
    const float* Wih = (const float*)d_in[2];
    const float* Whh = (const float*)d_in[3];
    const float* bih = (const float*)d_in[4];
    const float* bhh = (const float*)d_in[5];
    const float* fcw = (const float*)d_in[6];
    const float* fcb = (const float*)d_in[7];
    const float* cw  = (const float*)d_in[8];
    const float* cb  = (const float*)d_in[9];

    lstm_kernel<<<NB, 32>>>(x, Wih, Whh, bih, bhh);
    head_kernel<<<1, NB>>>(la, fcw, fcb, cw, cb, (float*)d_out);
}

// round 3
// speedup vs baseline: 1.2186x; 1.1810x over previous
#include <cuda_runtime.h>

#define NB   1024   // assets
#define NT   4096   // timesteps
#define NH   20     // hidden

// scratch: last hidden state per asset (no cudaMalloc allowed)
__device__ float g_hlast[NB * NH];

using u64 = unsigned long long;

__device__ __forceinline__ u64 pack2(float lo, float hi) {
    u64 r;
    asm("mov.b64 %0, {%1, %2};" : "=l"(r)
        : "r"(__float_as_uint(lo)), "r"(__float_as_uint(hi)));
    return r;
}
__device__ __forceinline__ float2 unpack2(u64 v) {
    unsigned lo, hi;
    asm("mov.b64 {%0, %1}, %2;" : "=r"(lo), "=r"(hi) : "l"(v));
    return make_float2(__uint_as_float(lo), __uint_as_float(hi));
}
__device__ __forceinline__ u64 ffma2(u64 a, u64 b, u64 c) {
    u64 d;
    asm("fma.rn.f32x2 %0, %1, %2, %3;" : "=l"(d) : "l"(a), "l"(b), "l"(c));
    return d;
}
__device__ __forceinline__ u64 add2(u64 a, u64 b) {
    u64 d;
    asm("add.rn.f32x2 %0, %1, %2;" : "=l"(d) : "l"(a), "l"(b));
    return d;
}
__device__ __forceinline__ float ex2a(float x) {
    float y; asm("ex2.approx.f32 %0, %1;" : "=f"(y) : "f"(x)); return y;
}
__device__ __forceinline__ float rcpa(float x) {
    float y; asm("rcp.approx.f32 %0, %1;" : "=f"(y) : "f"(x)); return y;
}
__device__ __forceinline__ float tanha(float x) {
    float y; asm("tanh.approx.f32 %0, %1;" : "=f"(y) : "f"(x)); return y;
}

#define LOG2E  1.44269504088896340f
#define LOG2E2 2.88539008177792681f

// one warp == one asset. Lane l owns gates l (A), l+32 (B), and (l<16) l+64 (C).
// Gate order (torch): i[0,20) f[20,40) g[40,60) o[60,80).
//   A-gates: sigmoid (precise, ex2-folded).  B-gates: sigmoid or tanh (precise).
//   C-gates: all o (sigmoid via tanh.approx, 0.5-folded).
__global__ void __launch_bounds__(32)
lstm_kernel(const float* __restrict__ x,
            const float* __restrict__ Wih,
            const float* __restrict__ Whh,
            const float* __restrict__ bih,
            const float* __restrict__ bhh)
{
    const int a = blockIdx.x;
    const int l = threadIdx.x;
    const bool hasC = (l < 16);

    __shared__ __align__(16) float s_h[2][24];

    const int gA = l;
    const int gB = l + 32;
    const int gC = hasC ? (l + 64) : 64;   // safe row when unused (scaled to 0)

    // activation pre-scales folded into weights/bias
    const bool  tB = (l >= 8 && l < 28);          // B tanh-gates
    const float sA = -LOG2E;
    const float sB = tB ? -LOG2E2 : -LOG2E;
    const float sC = hasC ? 0.5f : 0.0f;          // sigma(x)=0.5+0.5*tanh(x/2)
    const float aaB = tB ? 2.f : 1.f;
    const float abB = tB ? -1.f : 0.f;

    // ---- per-lane constants (scaled + packed) ----
    u64 wA[10], wB[10], wC[10];
    {
        const float2* ra = reinterpret_cast<const float2*>(Whh + gA * NH);
        const float2* rb = reinterpret_cast<const float2*>(Whh + gB * NH);
        const float2* rc = reinterpret_cast<const float2*>(Whh + gC * NH);
#pragma unroll
        for (int k = 0; k < 10; k++) {
            float2 va = ra[k], vb = rb[k], vc = rc[k];
            wA[k] = pack2(sA * va.x, sA * va.y);
            wB[k] = pack2(sB * vb.x, sB * vb.y);
            wC[k] = pack2(sC * vc.x, sC * vc.y);
        }
    }
    const u64 wiA01 = pack2(sA * Wih[gA*3+0], sA * Wih[gA*3+1]);
    const u64 wiA2z = pack2(sA * Wih[gA*3+2], 0.f);
    const u64 wiB01 = pack2(sB * Wih[gB*3+0], sB * Wih[gB*3+1]);
    const u64 wiB2z = pack2(sB * Wih[gB*3+2], 0.f);
    const u64 wiC01 = pack2(sC * Wih[gC*3+0], sC * Wih[gC*3+1]);
    const u64 wiC2z = pack2(sC * Wih[gC*3+2], 0.f);
    const u64 bA2 = pack2(sA * (bih[gA] + bhh[gA]), 0.f);
    const u64 bB2 = pack2(sB * (bih[gB] + bhh[gB]), 0.f);
    const u64 bC2 = pack2(sC * (bih[gC] + bhh[gC]), 0.f);
    const u64 ZZ  = 0ull;

    // gather: producer-side merges + 3 shuffles
    const bool mF = (l >= 20);     // lanes 20..31 provide actA, 0..7 provide actB
    const bool mO = (l >= 28);     // lanes 28..31 provide actB, 0..15 provide actC
    const int cF = (20 + l) & 31;
    const int cG = (8  + l) & 31;
    const int cO = (28 + l) & 31;

    // ---- x as float4 groups: x[f][a][t], contiguous in t ----
    const float4* p0 = reinterpret_cast<const float4*>(x + (size_t)a * NT);
    const float4* p1 = p0 + (size_t)NB * NT / 4;
    const float4* p2 = p1 + (size_t)NB * NT / 4;

    float4 cx0 = p0[0], cx1 = p1[0], cx2 = p2[0];

    u64 hk[10];
#pragma unroll
    for (int k = 0; k < 10; k++) hk[k] = 0ull;
    float c = 0.f, hval = 0.f;

    auto step = [&](float X0, float X1, float X2, int buf) {
        const u64 x01 = pack2(X0, X1);
        const u64 x22 = pack2(X2, X2);
        // acc init: bias + x-part (issues before hk arrives; off critical path)
        u64 a1 = ffma2(x01, wiA01, bA2);
        u64 a2 = ffma2(x22, wiA2z, ZZ);
        u64 b1 = ffma2(x01, wiB01, bB2);
        u64 b2 = ffma2(x22, wiB2z, ZZ);
        u64 c1 = ffma2(x01, wiC01, bC2);
        u64 c2 = ffma2(x22, wiC2z, ZZ);
#pragma unroll
        for (int k = 0; k < 5; k++) {
            a1 = ffma2(hk[2*k],   wA[2*k],   a1);
            a2 = ffma2(hk[2*k+1], wA[2*k+1], a2);
            b1 = ffma2(hk[2*k],   wB[2*k],   b1);
            b2 = ffma2(hk[2*k+1], wB[2*k+1], b2);
            c1 = ffma2(hk[2*k],   wC[2*k],   c1);
            c2 = ffma2(hk[2*k+1], wC[2*k+1], c2);
        }
        float2 pA = unpack2(add2(a1, a2));
        float2 pB = unpack2(add2(b1, b2));
        float2 pC = unpack2(add2(c1, c2));
        const float vA = pA.x + pA.y;   // already scaled by -log2e
        const float vB = pB.x + pB.y;   // scaled by -log2e / -2log2e
        const float vC = pC.x + pC.y;   // scaled by 0.5

        const float actA = rcpa(1.0f + ex2a(vA));              // sigmoid (precise)
        const float actB = fmaf(aaB, rcpa(1.0f + ex2a(vB)), abB); // sig/tanh (precise)
        const float actC = fmaf(0.5f, tanha(vC), 0.5f);        // o-gate (approx, safe)

        const float mrgF = mF ? actA : actB;
        const float mrgO = mO ? actB : actC;
        const float f  = __shfl_sync(0xffffffffu, mrgF, cF);
        const float gg = __shfl_sync(0xffffffffu, actB, cG);
        const float o  = __shfl_sync(0xffffffffu, mrgO, cO);
        const float i  = actA;     // unit u's i-gate is lane-local

        const float cn = fmaf(f, c, i * gg);
        c = cn;
        hval = o * tanha(cn);      // approx tanh(c): non-accumulating

        if (l < NH) s_h[buf][l] = hval;
        __syncwarp();
        const ulonglong2* hp = reinterpret_cast<const ulonglong2*>(s_h[buf]);
        ulonglong2 q;
        q = hp[0]; hk[0] = q.x; hk[1] = q.y;
        q = hp[1]; hk[2] = q.x; hk[3] = q.y;
        q = hp[2]; hk[4] = q.x; hk[5] = q.y;
        q = hp[3]; hk[6] = q.x; hk[7] = q.y;
        q = hp[4]; hk[8] = q.x; hk[9] = q.y;
        // next step writes the other buffer: no trailing sync needed
    };

#pragma unroll 1
    for (int t4 = 0; t4 < NT/4 - 1; t4++) {
        const float4 nx0 = p0[t4 + 1];
        const float4 nx1 = p1[t4 + 1];
        const float4 nx2 = p2[t4 + 1];
        step(cx0.x, cx1.x, cx2.x, 0);
        step(cx0.y, cx1.y, cx2.y, 1);
        step(cx0.z, cx1.z, cx2.z, 0);
        step(cx0.w, cx1.w, cx2.w, 1);
        cx0 = nx0; cx1 = nx1; cx2 = nx2;
    }
    // peeled last group (no prefetch)
    step(cx0.x, cx1.x, cx2.x, 0);
    step(cx0.y, cx1.y, cx2.y, 1);
    step(cx0.z, cx1.z, cx2.z, 0);
    step(cx0.w, cx1.w, cx2.w, 1);

    if (l < NH) g_hlast[a * NH + l] = hval;
}

// head: fc + 1x1 conv compose linearly: z_b = cw0*la_b + relu(h_b)·u + s
__global__ void __launch_bounds__(NB)
head_kernel(const float* __restrict__ la,
            const float* __restrict__ fcw,
            const float* __restrict__ fcb,
            const float* __restrict__ cw,
            const float* __restrict__ cb,
            float* __restrict__ out)
{
    const int b = threadIdx.x;
    __shared__ float s_u[NH];
    __shared__ float s_s;
    __shared__ float s_red[32];
    __shared__ float s_bcast;

    if (b < NH) {
        float u = 0.f;
#pragma unroll
        for (int j = 0; j < NH; j++) u = fmaf(cw[1 + j], fcw[j * NH + b], u);
        s_u[b] = u;
    }
    if (b == NH) {
        float s = cb[0];
#pragma unroll
        for (int j = 0; j < NH; j++) s = fmaf(cw[1 + j], fcb[j], s);
        s_s = s;
    }
    __syncthreads();

    float z = fmaf(cw[0], la[b], s_s);
    const float* h = &g_hlast[b * NH];
#pragma unroll
    for (int j = 0; j < NH; j++) z = fmaf(fmaxf(h[j], 0.f), s_u[j], z);

    float m = z;
#pragma unroll
    for (int off = 16; off > 0; off >>= 1)
        m = fmaxf(m, __shfl_xor_sync(0xffffffffu, m, off));
    if ((b & 31) == 0) s_red[b >> 5] = m;
    __syncthreads();
    if (b < 32) {
        float v = s_red[b];
#pragma unroll
        for (int off = 16; off > 0; off >>= 1)
            v = fmaxf(v, __shfl_xor_sync(0xffffffffu, v, off));
        if (b == 0) s_bcast = fmaxf(v, 1.0f);
    }
    __syncthreads();
    m = s_bcast;

    float e = __expf(z - m);
    float s = e;
#pragma unroll
    for (int off = 16; off > 0; off >>= 1)
        s += __shfl_xor_sync(0xffffffffu, s, off);
    if ((b & 31) == 0) s_red[b >> 5] = s;
    __syncthreads();
    if (b < 32) {
        float v = s_red[b];
#pragma unroll
        for (int off = 16; off > 0; off >>= 1)
            v += __shfl_xor_sync(0xffffffffu, v, off);
        if (b == 0) s_bcast = v + __expf(1.0f - m);
    }
    __syncthreads();
    const float denom = s_bcast;

    out[1 + b] = e / denom;
    if (b == 0) out[0] = __expf(1.0f - m) / denom;
}

extern "C" void kernel_launch(void* const* d_in, const int* in_sizes, int n_in,
                              void* d_out, int out_size)
{
    const float* x   = (const float*)d_in[0];
    const float* la  = (const float*)d_in[1];
    const float* Wih = (const float*)d_in[2];
    const float* Whh = (const float*)d_in[3];
    const float* bih = (const float*)d_in[4];
    const float* bhh = (const float*)d_in[5];
    const float* fcw = (const float*)d_in[6];
    const float* fcb = (const float*)d_in[7];
    const float* cw  = (const float*)d_in[8];
    const float* cb  = (const float*)d_in[9];

    lstm_kernel<<<NB, 32>>>(x, Wih, Whh, bih, bhh);
    head_kernel<<<1, NB>>>(la, fcw, fcb, cw, cb, (float*)d_out);
}

// round 4
// speedup vs baseline: 1.5414x; 1.2648x over previous
#include <cuda_runtime.h>

#define NB   1024   // assets
#define NT   4096   // timesteps
#define NH   20     // hidden

// scratch: last hidden state per asset (no cudaMalloc allowed)
__device__ float g_hlast[NB * NH];

using u64 = unsigned long long;

__device__ __forceinline__ u64 pack2(float lo, float hi) {
    u64 r;
    asm("mov.b64 %0, {%1, %2};" : "=l"(r)
        : "r"(__float_as_uint(lo)), "r"(__float_as_uint(hi)));
    return r;
}
__device__ __forceinline__ float2 unpack2(u64 v) {
    unsigned lo, hi;
    asm("mov.b64 {%0, %1}, %2;" : "=r"(lo), "=r"(hi) : "l"(v));
    return make_float2(__uint_as_float(lo), __uint_as_float(hi));
}
__device__ __forceinline__ u64 ffma2(u64 a, u64 b, u64 c) {
    u64 d;
    asm("fma.rn.f32x2 %0, %1, %2, %3;" : "=l"(d) : "l"(a), "l"(b), "l"(c));
    return d;
}
__device__ __forceinline__ u64 add2(u64 a, u64 b) {
    u64 d;
    asm("add.rn.f32x2 %0, %1, %2;" : "=l"(d) : "l"(a), "l"(b));
    return d;
}
__device__ __forceinline__ float tanha(float x) {
    float y; asm("tanh.approx.f32 %0, %1;" : "=f"(y) : "f"(x)); return y;
}

// ============================================================================
// 2 assets per warp. Half h = l>>4 handles asset 2*bid+h; q = l&15.
// Lane q of a half owns gates {16s + q : s in 0..4} of its asset.
// Gate order (torch): i[0,20) f[20,40) g[40,60) o[60,80).
// All activations via tanh.approx: sigmoid(x) = 0.5*tanh(x/2)+0.5 (0.5 folded
// into weights), tanh gate used raw.
// Primary unit u=q (all 16 lanes), secondary unit u=16+q (lanes q<4).
// ============================================================================
__global__ void __launch_bounds__(32)
lstm_kernel(const float* __restrict__ x,
            const float* __restrict__ Wih,
            const float* __restrict__ Whh,
            const float* __restrict__ bih,
            const float* __restrict__ bhh)
{
    const int l  = threadIdx.x;
    const int q  = l & 15;
    const int hb = l & 16;                    // shuffle half-base
    const int asset = 2 * blockIdx.x + (l >> 4);

    // h exchange: [buf][asset-half][24 floats]
    __shared__ __align__(16) float s_h[2][2][24];

    // ---- per-slot constants (same weights both halves) ----
    u64 wS[5][10];     // W_hh rows, activation-scaled, packed pairs
    u64 wi01[5], wi2z[5], bia[5];
    float aa[5], ab[5];
#pragma unroll
    for (int s = 0; s < 5; s++) {
        const int g = 16 * s + q;
        const bool tg = (g >= 40 && g < 60);           // tanh gate
        const float sc = tg ? 1.0f : 0.5f;
        aa[s] = tg ? 1.0f : 0.5f;
        ab[s] = tg ? 0.0f : 0.5f;
        const float2* rw = reinterpret_cast<const float2*>(Whh + g * NH);
#pragma unroll
        for (int k = 0; k < 10; k++) {
            float2 v = rw[k];
            wS[s][k] = pack2(sc * v.x, sc * v.y);
        }
        wi01[s] = pack2(sc * Wih[g*3+0], sc * Wih[g*3+1]);
        wi2z[s] = pack2(sc * Wih[g*3+2], 0.f);
        bia[s]  = pack2(sc * (bih[g] + bhh[g]), 0.f);
    }
    const u64 ZZ = 0ull;

    // gather shuffle indices (within half)
    const int cF = hb | ((q + 4)  & 15);
    const int cG = hb | ((q + 8)  & 15);
    const int cO = hb | ((q + 12) & 15);
    const bool pF = (q >= 4);    // producer-side merge selectors
    const bool pG = (q >= 8);
    const bool pO = (q >= 12);

    // ---- x pointers (per half): x[f][asset][t], float4 groups ----
    const float4* p0 = reinterpret_cast<const float4*>(x + (size_t)asset * NT);
    const float4* p1 = p0 + (size_t)NB * NT / 4;
    const float4* p2 = p1 + (size_t)NB * NT / 4;

    float4 cx0 = p0[0], cx1 = p1[0], cx2 = p2[0];

    u64 hk[10];
#pragma unroll
    for (int k = 0; k < 10; k++) hk[k] = 0ull;
    float c1 = 0.f, c2 = 0.f, h1 = 0.f, h2 = 0.f;

    float* myh = s_h[0][l >> 4];   // rebased per buf inside step

    auto step = [&](float X0, float X1, float X2, int buf) {
        const u64 x01 = pack2(X0, X1);
        const u64 x22 = pack2(X2, X2);

        float act[5];
#pragma unroll
        for (int s = 0; s < 5; s++) {
            u64 A = ffma2(x01, wi01[s], bia[s]);
            u64 B = ffma2(x22, wi2z[s], ZZ);
#pragma unroll
            for (int k = 0; k < 5; k++) {
                A = ffma2(hk[2*k],   wS[s][2*k],   A);
                B = ffma2(hk[2*k+1], wS[s][2*k+1], B);
            }
            float2 p = unpack2(add2(A, B));
            act[s] = fmaf(aa[s], tanha(p.x + p.y), ab[s]);
        }

        // primary gather (merged producers)
        const float mF = pF ? act[1] : act[2];
        const float mG = pG ? act[2] : act[3];
        const float mO = pO ? act[3] : act[4];
        const float f1 = __shfl_sync(0xffffffffu, mF, cF);
        const float g1 = __shfl_sync(0xffffffffu, mG, cG);
        const float o1 = __shfl_sync(0xffffffffu, mO, cO);
        const float i1 = act[0];
        // secondary gather (unit 16+q, meaningful for q<4)
        const float f2 = __shfl_sync(0xffffffffu, act[2], cF);
        const float g2 = __shfl_sync(0xffffffffu, act[3], cG);
        const float o2 = __shfl_sync(0xffffffffu, act[4], cO);
        const float i2 = act[1];

        c1 = fmaf(f1, c1, i1 * g1);
        h1 = o1 * tanha(c1);
        c2 = fmaf(f2, c2, i2 * g2);
        h2 = o2 * tanha(c2);

        float* hbuf = s_h[buf][l >> 4];
        hbuf[q] = h1;
        if (q < 4) hbuf[16 + q] = h2;
        __syncwarp();
        const ulonglong2* hp = reinterpret_cast<const ulonglong2*>(hbuf);
        ulonglong2 r;
        r = hp[0]; hk[0] = r.x; hk[1] = r.y;
        r = hp[1]; hk[2] = r.x; hk[3] = r.y;
        const u64* hp64 = reinterpret_cast<const u64*>(hbuf);
        hk[4] = hp64[4]; hk[5] = hp64[5];
        hk[6] = hp64[6]; hk[7] = hp64[7];
        hk[8] = hp64[8]; hk[9] = hp64[9];
        // next step writes the other buffer: no trailing sync
        (void)myh;
    };

#pragma unroll 1
    for (int t4 = 0; t4 < NT/4 - 1; t4++) {
        const float4 nx0 = p0[t4 + 1];
        const float4 nx1 = p1[t4 + 1];
        const float4 nx2 = p2[t4 + 1];
        step(cx0.x, cx1.x, cx2.x, 0);
        step(cx0.y, cx1.y, cx2.y, 1);
        step(cx0.z, cx1.z, cx2.z, 0);
        step(cx0.w, cx1.w, cx2.w, 1);
        cx0 = nx0; cx1 = nx1; cx2 = nx2;
    }
    step(cx0.x, cx1.x, cx2.x, 0);
    step(cx0.y, cx1.y, cx2.y, 1);
    step(cx0.z, cx1.z, cx2.z, 0);
    step(cx0.w, cx1.w, cx2.w, 1);

    g_hlast[asset * NH + q] = h1;
    if (q < 4) g_hlast[asset * NH + 16 + q] = h2;
}

// head: fc + 1x1 conv compose linearly: z_b = cw0*la_b + relu(h_b)·u + s
__global__ void __launch_bounds__(NB)
head_kernel(const float* __restrict__ la,
            const float* __restrict__ fcw,
            const float* __restrict__ fcb,
            const float* __restrict__ cw,
            const float* __restrict__ cb,
            float* __restrict__ out)
{
    const int b = threadIdx.x;
    __shared__ float s_u[NH];
    __shared__ float s_s;
    __shared__ float s_red[32];
    __shared__ float s_bcast;

    if (b < NH) {
        float u = 0.f;
#pragma unroll
        for (int j = 0; j < NH; j++) u = fmaf(cw[1 + j], fcw[j * NH + b], u);
        s_u[b] = u;
    }
    if (b == NH) {
        float s = cb[0];
#pragma unroll
        for (int j = 0; j < NH; j++) s = fmaf(cw[1 + j], fcb[j], s);
        s_s = s;
    }
    __syncthreads();

    float z = fmaf(cw[0], la[b], s_s);
    const float* h = &g_hlast[b * NH];
#pragma unroll
    for (int j = 0; j < NH; j++) z = fmaf(fmaxf(h[j], 0.f), s_u[j], z);

    float m = z;
#pragma unroll
    for (int off = 16; off > 0; off >>= 1)
        m = fmaxf(m, __shfl_xor_sync(0xffffffffu, m, off));
    if ((b & 31) == 0) s_red[b >> 5] = m;
    __syncthreads();
    if (b < 32) {
        float v = s_red[b];
#pragma unroll
        for (int off = 16; off > 0; off >>= 1)
            v = fmaxf(v, __shfl_xor_sync(0xffffffffu, v, off));
        if (b == 0) s_bcast = fmaxf(v, 1.0f);
    }
    __syncthreads();
    m = s_bcast;

    float e = __expf(z - m);
    float s = e;
#pragma unroll
    for (int off = 16; off > 0; off >>= 1)
        s += __shfl_xor_sync(0xffffffffu, s, off);
    if ((b & 31) == 0) s_red[b >> 5] = s;
    __syncthreads();
    if (b < 32) {
        float v = s_red[b];
#pragma unroll
        for (int off = 16; off > 0; off >>= 1)
            v += __shfl_xor_sync(0xffffffffu, v, off);
        if (b == 0) s_bcast = v + __expf(1.0f - m);
    }
    __syncthreads();
    const float denom = s_bcast;

    out[1 + b] = e / denom;
    if (b == 0) out[0] = __expf(1.0f - m) / denom;
}

extern "C" void kernel_launch(void* const* d_in, const int* in_sizes, int n_in,
                              void* d_out, int out_size)
{
    const float* x   = (const float*)d_in[0];
    const float* la  = (const float*)d_in[1];
    const float* Wih = (const float*)d_in[2];
    const float* Whh = (const float*)d_in[3];
    const float* bih = (const float*)d_in[4];
    const float* bhh = (const float*)d_in[5];
    const float* fcw = (const float*)d_in[6];
    const float* fcb = (const float*)d_in[7];
    const float* cw  = (const float*)d_in[8];
    const float* cb  = (const float*)d_in[9];

    lstm_kernel<<<NB / 2, 32>>>(x, Wih, Whh, bih, bhh);
    head_kernel<<<1, NB>>>(la, fcw, fcb, cw, cb, (float*)d_out);
}

// round 5
// speedup vs baseline: 1.7540x; 1.1380x over previous
#include <cuda_runtime.h>

#define NB   1024   // assets
#define NT   4096   // timesteps
#define NH   20     // hidden

__device__ float g_hlast[NB * NH];

using u64 = unsigned long long;

__device__ __forceinline__ u64 pack2(float lo, float hi) {
    u64 r;
    asm("mov.b64 %0, {%1, %2};" : "=l"(r)
        : "r"(__float_as_uint(lo)), "r"(__float_as_uint(hi)));
    return r;
}
__device__ __forceinline__ float2 unpack2(u64 v) {
    unsigned lo, hi;
    asm("mov.b64 {%0, %1}, %2;" : "=r"(lo), "=r"(hi) : "l"(v));
    return make_float2(__uint_as_float(lo), __uint_as_float(hi));
}
__device__ __forceinline__ u64 ffma2(u64 a, u64 b, u64 c) {
    u64 d;
    asm("fma.rn.f32x2 %0, %1, %2, %3;" : "=l"(d) : "l"(a), "l"(b), "l"(c));
    return d;
}
__device__ __forceinline__ float tanha(float x) {
    float y; asm("tanh.approx.f32 %0, %1;" : "=f"(y) : "f"(x)); return y;
}

// ============================================================================
// 2 assets per warp; half = l>>4, q = l&15, asset = 2*bid + half.
// Lane q slots s=0..3: gate 20*s+q  == unit q's i,f,g,o  (ALL LANE-LOCAL).
// Slot s=4: gate 20*(q&3) + 16 + (q>>2)  (unit 16+(q>>2), type q&3).
// Sigmoid via 0.5*tanh(x/2)+0.5 (0.5 folded into weights); g-gate raw tanh.
// h[0..15] exchanged via smem; h[16..19] stays in regs of lanes q<4 and is
// distributed by shuffles into hk[8..9] at the start of the next step.
// ============================================================================
__global__ void __launch_bounds__(32)
lstm_kernel(const float* __restrict__ x,
            const float* __restrict__ Wih,
            const float* __restrict__ Whh,
            const float* __restrict__ bih,
            const float* __restrict__ bhh)
{
    const int l  = threadIdx.x;
    const int q  = l & 15;
    const int hb = l & 16;
    const int half = l >> 4;
    const int asset = 2 * blockIdx.x + half;

    __shared__ __align__(16) float s_h[2][2][16];   // [buf][half][unit 0..15]

    // ---- per-slot constants ----
    u64 wS[5][10], wi01[5], wi2z[5], bia[5];
    int gate[5];
#pragma unroll
    for (int s = 0; s < 4; s++) gate[s] = 20 * s + q;
    gate[4] = 20 * (q & 3) + 16 + (q >> 2);
    // activation fold for slot 4 (lane-dependent type)
    const bool t4 = ((q & 3) == 2);
    const float aa4 = t4 ? 1.0f : 0.5f;
    const float ab4 = t4 ? 0.0f : 0.5f;
#pragma unroll
    for (int s = 0; s < 5; s++) {
        const int g = gate[s];
        const bool tg = (s == 2) || (s == 4 && t4);
        const float sc = tg ? 1.0f : 0.5f;
        const float2* rw = reinterpret_cast<const float2*>(Whh + g * NH);
#pragma unroll
        for (int k = 0; k < 10; k++) {
            float2 v = rw[k];
            wS[s][k] = pack2(sc * v.x, sc * v.y);
        }
        wi01[s] = pack2(sc * Wih[g*3+0], sc * Wih[g*3+1]);
        wi2z[s] = pack2(sc * Wih[g*3+2], 0.f);
        bia[s]  = pack2(sc * (bih[g] + bhh[g]), 0.f);
    }

    // secondary gather sources: unit 16+q's type m comes from lane hb|(4q+m)
    const int sI = hb | ((4 * q + 0) & 15);
    const int sF = hb | ((4 * q + 1) & 15);
    const int sG = hb | ((4 * q + 2) & 15);
    const int sO = hb | ((4 * q + 3) & 15);

    // ---- x pointers: x[f][asset][t], float4 groups ----
    const float4* p0 = reinterpret_cast<const float4*>(x + (size_t)asset * NT);
    const float4* p1 = p0 + (size_t)NB * NT / 4;
    const float4* p2 = p1 + (size_t)NB * NT / 4;

    float4 cx0 = p0[0], cx1 = p1[0], cx2 = p2[0];

    u64 hk[10];
#pragma unroll
    for (int k = 0; k < 10; k++) hk[k] = 0ull;
    float c1 = 0.f, c2 = 0.f, h1 = 0.f, h2 = 0.f;

    // first step's init accumulators (bias + x-part)
    u64 ini[5];
    {
        const u64 x01 = pack2(cx0.x, cx1.x);
        const u64 x22 = pack2(cx2.x, cx2.x);
#pragma unroll
        for (int s = 0; s < 5; s++)
            ini[s] = ffma2(x01, wi01[s], ffma2(x22, wi2z[s], bia[s]));
    }

    // Xn0/Xn1/Xn2 = x of the NEXT step (for the shadow init)
    auto step = [&](float Xn0, float Xn1, float Xn2, int buf) {
        // single 10-link dot chain per slot on top of preloaded init
        float act[5];
#pragma unroll
        for (int s = 0; s < 5; s++) {
            u64 acc = ini[s];
#pragma unroll
            for (int k = 0; k < 10; k++) acc = ffma2(hk[k], wS[s][k], acc);
            float2 p = unpack2(acc);
            const float th = tanha(p.x + p.y);
            act[s] = (s == 2) ? th
                   : (s == 4) ? fmaf(aa4, th, ab4)
                              : fmaf(0.5f, th, 0.5f);
        }

        // secondary gather (4 shuffles, off the primary path)
        const float i2 = __shfl_sync(0xffffffffu, act[4], sI);
        const float f2 = __shfl_sync(0xffffffffu, act[4], sF);
        const float g2 = __shfl_sync(0xffffffffu, act[4], sG);
        const float o2 = __shfl_sync(0xffffffffu, act[4], sO);

        // primary update: fully lane-local
        c1 = fmaf(act[1], c1, act[0] * act[2]);
        h1 = act[3] * tanha(c1);

        // secondary update (meaningful for q<4; junk elsewhere, never stored)
        c2 = fmaf(f2, c2, i2 * g2);
        h2 = o2 * tanha(c2);

        s_h[buf][half][q] = h1;

        // next step's init in the sync shadow
        const u64 x01n = pack2(Xn0, Xn1);
        const u64 x22n = pack2(Xn2, Xn2);
#pragma unroll
        for (int s = 0; s < 5; s++)
            ini[s] = ffma2(x01n, wi01[s], ffma2(x22n, wi2z[s], bia[s]));

        __syncwarp();

        // reload hk[0..7] from smem; hk[8..9] from h2 via shuffles
        const ulonglong2* hp = reinterpret_cast<const ulonglong2*>(s_h[buf][half]);
        ulonglong2 r;
        r = hp[0]; hk[0] = r.x; hk[1] = r.y;
        r = hp[1]; hk[2] = r.x; hk[3] = r.y;
        r = hp[2]; hk[4] = r.x; hk[5] = r.y;
        r = hp[3]; hk[6] = r.x; hk[7] = r.y;
        hk[8] = pack2(__shfl_sync(0xffffffffu, h2, hb | 0),
                      __shfl_sync(0xffffffffu, h2, hb | 1));
        hk[9] = pack2(__shfl_sync(0xffffffffu, h2, hb | 2),
                      __shfl_sync(0xffffffffu, h2, hb | 3));
    };

#pragma unroll 1
    for (int t4 = 0; t4 < NT/4 - 1; t4++) {
        const float4 nx0 = p0[t4 + 1];
        const float4 nx1 = p1[t4 + 1];
        const float4 nx2 = p2[t4 + 1];
        step(cx0.y, cx1.y, cx2.y, 0);
        step(cx0.z, cx1.z, cx2.z, 1);
        step(cx0.w, cx1.w, cx2.w, 0);
        step(nx0.x, nx1.x, nx2.x, 1);
        cx0 = nx0; cx1 = nx1; cx2 = nx2;
    }
    // last group: next-x args are don't-cares (reuse current)
    step(cx0.y, cx1.y, cx2.y, 0);
    step(cx0.z, cx1.z, cx2.z, 1);
    step(cx0.w, cx1.w, cx2.w, 0);
    step(cx0.w, cx1.w, cx2.w, 1);

    g_hlast[asset * NH + q] = h1;                 // units 0..15
    if (q < 4) g_hlast[asset * NH + 16 + q] = h2; // units 16..19
}

// head: fc + 1x1 conv compose linearly: z_b = cw0*la_b + relu(h_b)·u + s
__global__ void __launch_bounds__(NB)
head_kernel(const float* __restrict__ la,
            const float* __restrict__ fcw,
            const float* __restrict__ fcb,
            const float* __restrict__ cw,
            const float* __restrict__ cb,
            float* __restrict__ out)
{
    const int b = threadIdx.x;
    __shared__ float s_u[NH];
    __shared__ float s_s;
    __shared__ float s_red[32];
    __shared__ float s_bcast;

    if (b < NH) {
        float u = 0.f;
#pragma unroll
        for (int j = 0; j < NH; j++) u = fmaf(cw[1 + j], fcw[j * NH + b], u);
        s_u[b] = u;
    }
    if (b == NH) {
        float s = cb[0];
#pragma unroll
        for (int j = 0; j < NH; j++) s = fmaf(cw[1 + j], fcb[j], s);
        s_s = s;
    }
    __syncthreads();

    float z = fmaf(cw[0], la[b], s_s);
    const float* h = &g_hlast[b * NH];
#pragma unroll
    for (int j = 0; j < NH; j++) z = fmaf(fmaxf(h[j], 0.f), s_u[j], z);

    float m = z;
#pragma unroll
    for (int off = 16; off > 0; off >>= 1)
        m = fmaxf(m, __shfl_xor_sync(0xffffffffu, m, off));
    if ((b & 31) == 0) s_red[b >> 5] = m;
    __syncthreads();
    if (b < 32) {
        float v = s_red[b];
#pragma unroll
        for (int off = 16; off > 0; off >>= 1)
            v = fmaxf(v, __shfl_xor_sync(0xffffffffu, v, off));
        if (b == 0) s_bcast = fmaxf(v, 1.0f);
    }
    __syncthreads();
    m = s_bcast;

    float e = __expf(z - m);
    float s = e;
#pragma unroll
    for (int off = 16; off > 0; off >>= 1)
        s += __shfl_xor_sync(0xffffffffu, s, off);
    if ((b & 31) == 0) s_red[b >> 5] = s;
    __syncthreads();
    if (b < 32) {
        float v = s_red[b];
#pragma unroll
        for (int off = 16; off > 0; off >>= 1)
            v += __shfl_xor_sync(0xffffffffu, v, off);
        if (b == 0) s_bcast = v + __expf(1.0f - m);
    }
    __syncthreads();
    const float denom = s_bcast;

    out[1 + b] = e / denom;
    if (b == 0) out[0] = __expf(1.0f - m) / denom;
}

extern "C" void kernel_launch(void* const* d_in, const int* in_sizes, int n_in,
                              void* d_out, int out_size)
{
    const float* x   = (const float*)d_in[0];
    const float* la  = (const float*)d_in[1];
    const float* Wih = (const float*)d_in[2];
    const float* Whh = (const float*)d_in[3];
    const float* bih = (const float*)d_in[4];
    const float* bhh = (const float*)d_in[5];
    const float* fcw = (const float*)d_in[6];
    const float* fcb = (const float*)d_in[7];
    const float* cw  = (const float*)d_in[8];
    const float* cb  = (const float*)d_in[9];

    lstm_kernel<<<NB / 2, 32>>>(x, Wih, Whh, bih, bhh);
    head_kernel<<<1, NB>>>(la, fcw, fcb, cw, cb, (float*)d_out);
}